// round 2
// baseline (speedup 1.0000x reference)
#include <cuda_runtime.h>
#include <math.h>
#include <float.h>

// Problem constants
#define NN 50000
#define EE 800000
#define ET (EE+NN)          // edges + self loops = 850000
#define HH 4
#define HC 256              // H*C
#define GG 256
#define EDIM 16
#define NEG 0.2f
#define BNEPS 1e-5f
#define CAP 1024            // max in-degree handled per node (avg ~17, Poisson)
#define NBLK_SCAN 196       // ceil(NN/256)

// ---------------- device scratch (static, no allocs) ----------------
__device__ float g_h [(size_t)NN*HC];
__device__ float g_t0[(size_t)NN*HC];
__device__ float g_t1[(size_t)NN*HC];
__device__ float g_alpha[(size_t)ET*HH];
__device__ float g_asrc[NN*HH];
__device__ float g_adst[NN*HH];
__device__ int   g_deg[NN];
__device__ int   g_rowptr[NN+1];
__device__ int   g_cursor[NN];
__device__ int   g_csr[ET];
__device__ int   g_bsum[256];
__device__ float g_ps1[200*HC];
__device__ float g_ps2[200*HC];
__device__ float g_scale[HC];
__device__ float g_shift[HC];
__device__ float g_ve[EDIM*HH];
__device__ float g_sl[HH];
__device__ float g_mpart[256*EDIM];

// ---------------- small init ----------------
__global__ void k_zero() {
    int i = blockIdx.x*256 + threadIdx.x;
    if (i < NN) g_deg[i] = 0;
}

// ---------------- edge_attr mean (partials, deterministic) ----------------
__global__ void k_edge_mean(const float* __restrict__ ea) {
    // 256 blocks, 256 threads. block b handles rows [b*3125, (b+1)*3125)
    __shared__ float sm[256];
    int t = threadIdx.x;
    int col = t & 15, r = t >> 4;
    int b = blockIdx.x;
    float s = 0.f;
    const float* base = ea + (size_t)b*3125*EDIM;
    for (int row = r; row < 3125; row += 16)
        s += base[row*EDIM + col];
    sm[t] = s; __syncthreads();
    if (t < EDIM) {
        float tot = 0.f;
        #pragma unroll
        for (int rr = 0; rr < 16; rr++) tot += sm[rr*16 + t];
        g_mpart[b*EDIM + t] = tot;
    }
}

// ve[d][h] = sum_c We0[d, h*64+c]*att_e0[h,c];  sl[h] = mean_attr . ve[:,h]
__global__ void k_ve(const float* __restrict__ We0, const float* __restrict__ atte) {
    __shared__ float s_mean[EDIM];
    __shared__ float s_ve[EDIM*HH];
    int t = threadIdx.x; // 64 threads
    if (t < EDIM) {
        float s = 0.f;
        for (int b = 0; b < 256; b++) s += g_mpart[b*EDIM + t];
        s_mean[t] = s * (1.0f/EE);
    }
    {
        int d = t >> 2, hd = t & 3;
        float s = 0.f;
        for (int c = 0; c < 64; c++)
            s += We0[d*HC + hd*64 + c] * atte[hd*64 + c];
        s_ve[t] = s; g_ve[t] = s;
    }
    __syncthreads();
    if (t < HH) {
        float s = 0.f;
        for (int d = 0; d < EDIM; d++) s += s_mean[d] * s_ve[d*4 + t];
        g_sl[t] = s;
    }
}

// ---------------- CSR build ----------------
__global__ void k_count(const int* __restrict__ ei) {
    int e = blockIdx.x*256 + threadIdx.x;
    if (e >= ET) return;
    int d = (e < EE) ? ei[EE + e] : (e - EE);
    atomicAdd(&g_deg[d], 1);
}

__global__ void k_scan1() {
    __shared__ int sm[256];
    int t = threadIdx.x, i = blockIdx.x*256 + t;
    int v = (i < NN) ? g_deg[i] : 0;
    sm[t] = v; __syncthreads();
    for (int o = 1; o < 256; o <<= 1) {
        int x = (t >= o) ? sm[t-o] : 0;
        __syncthreads();
        sm[t] += x;
        __syncthreads();
    }
    if (i < NN) g_rowptr[i] = sm[t] - v;          // local exclusive
    if (t == 255) g_bsum[blockIdx.x] = sm[255];
}

__global__ void k_scan2() {
    __shared__ int sm[256];
    int t = threadIdx.x;
    int v = (t < NBLK_SCAN) ? g_bsum[t] : 0;
    sm[t] = v; __syncthreads();
    for (int o = 1; o < 256; o <<= 1) {
        int x = (t >= o) ? sm[t-o] : 0;
        __syncthreads();
        sm[t] += x;
        __syncthreads();
    }
    g_bsum[t] = sm[t] - v;                        // exclusive block offsets
}

__global__ void k_scan3() {
    int t = threadIdx.x, i = blockIdx.x*256 + t;
    if (i < NN) {
        int rp = g_rowptr[i] + g_bsum[blockIdx.x];
        g_rowptr[i] = rp;
        g_cursor[i] = rp;
    }
    if (i == 0) g_rowptr[NN] = ET;
}

__global__ void k_scatter(const int* __restrict__ ei) {
    int e = blockIdx.x*256 + threadIdx.x;
    if (e >= ET) return;
    int d = (e < EE) ? ei[EE + e] : (e - EE);
    int pos = atomicAdd(&g_cursor[d], 1);
    g_csr[pos] = e;
}

// ---------------- SGEMM: C[M,256] = A[M,K] @ B[K,256] ----------------
__global__ void __launch_bounds__(256) k_gemm(const float* __restrict__ A,
                                              const float* __restrict__ B,
                                              float* __restrict__ C,
                                              int M, int K) {
    __shared__ float As[16][128];
    __shared__ float Bs[16][64];
    int tid = threadIdx.x;
    int bm = blockIdx.x * 128;
    int bn = blockIdx.y * 64;
    int tr = tid >> 4, tc = tid & 15;
    float acc[8][4];
    #pragma unroll
    for (int i = 0; i < 8; i++)
        #pragma unroll
        for (int j = 0; j < 4; j++) acc[i][j] = 0.f;

    for (int k0 = 0; k0 < K; k0 += 16) {
        #pragma unroll
        for (int i = 0; i < 2; i++) {
            int l = tid + i*256;
            int row = l >> 2, kq = l & 3;
            float4 v = make_float4(0.f,0.f,0.f,0.f);
            int gr = bm + row;
            if (gr < M) v = *(const float4*)(A + (size_t)gr*K + k0 + kq*4);
            As[kq*4+0][row] = v.x; As[kq*4+1][row] = v.y;
            As[kq*4+2][row] = v.z; As[kq*4+3][row] = v.w;
        }
        {
            int k = tid >> 4, c4 = (tid & 15)*4;
            float4 v = *(const float4*)(B + (size_t)(k0+k)*HC + bn + c4);
            *(float4*)&Bs[k][c4] = v;
        }
        __syncthreads();
        #pragma unroll
        for (int kk = 0; kk < 16; kk++) {
            float4 a0 = *(float4*)&As[kk][tr*8];
            float4 a1 = *(float4*)&As[kk][tr*8+4];
            float4 b0 = *(float4*)&Bs[kk][tc*4];
            float av[8] = {a0.x,a0.y,a0.z,a0.w,a1.x,a1.y,a1.z,a1.w};
            float bv[4] = {b0.x,b0.y,b0.z,b0.w};
            #pragma unroll
            for (int i = 0; i < 8; i++)
                #pragma unroll
                for (int j = 0; j < 4; j++)
                    acc[i][j] += av[i]*bv[j];
        }
        __syncthreads();
    }
    #pragma unroll
    for (int i = 0; i < 8; i++) {
        int gr = bm + tr*8 + i;
        if (gr < M) {
            float4 v = make_float4(acc[i][0], acc[i][1], acc[i][2], acc[i][3]);
            *(float4*)(C + (size_t)gr*HC + bn + tc*4) = v;
        }
    }
}

// ---------------- per-node attention dot products ----------------
__global__ void k_nodealpha(const float* __restrict__ aS, const float* __restrict__ aD) {
    int n = blockIdx.x;
    int w = threadIdx.x >> 5, lane = threadIdx.x & 31;  // 128 threads: warp = head
    const float* hp = g_h + (size_t)n*HC + w*64;
    float v1 = hp[lane], v2 = hp[lane+32];
    float s = v1*aS[w*64+lane] + v2*aS[w*64+lane+32];
    float d = v1*aD[w*64+lane] + v2*aD[w*64+lane+32];
    #pragma unroll
    for (int o = 16; o; o >>= 1) {
        s += __shfl_xor_sync(0xffffffffu, s, o);
        d += __shfl_xor_sync(0xffffffffu, d, o);
    }
    if (lane == 0) { g_asrc[n*4+w] = s; g_adst[n*4+w] = d; }
}

// ---------------- per-edge alpha (leaky relu applied) ----------------
__global__ void k_edgealpha(const int* __restrict__ ei, const float* __restrict__ ea, int l0) {
    int e = blockIdx.x*256 + threadIdx.x;
    if (e >= ET) return;
    int s, d;
    if (e < EE) { s = ei[e]; d = ei[EE + e]; } else { s = d = e - EE; }
    float4 a = ((const float4*)g_asrc)[s];
    float4 b = ((const float4*)g_adst)[d];
    float al[4] = {a.x+b.x, a.y+b.y, a.z+b.z, a.w+b.w};
    if (l0) {
        if (e < EE) {
            const float* er = ea + (size_t)e*EDIM;
            float ex0=0.f, ex1=0.f, ex2=0.f, ex3=0.f;
            #pragma unroll
            for (int k = 0; k < EDIM; k++) {
                float v = er[k];
                ex0 += v*g_ve[k*4+0]; ex1 += v*g_ve[k*4+1];
                ex2 += v*g_ve[k*4+2]; ex3 += v*g_ve[k*4+3];
            }
            al[0]+=ex0; al[1]+=ex1; al[2]+=ex2; al[3]+=ex3;
        } else {
            al[0]+=g_sl[0]; al[1]+=g_sl[1]; al[2]+=g_sl[2]; al[3]+=g_sl[3];
        }
    }
    #pragma unroll
    for (int i = 0; i < 4; i++) al[i] = (al[i] >= 0.f) ? al[i] : NEG*al[i];
    ((float4*)g_alpha)[e] = make_float4(al[0], al[1], al[2], al[3]);
}

// ---------------- per-dst aggregation: softmax + weighted sum ----------------
__global__ void __launch_bounds__(256) k_aggregate(const int* __restrict__ ei,
                                                   const float* __restrict__ bias,
                                                   float* __restrict__ outp) {
    __shared__ int   s_eid[CAP];
    __shared__ int   s_src[CAP];
    __shared__ float s_a[CAP*4];
    __shared__ float s_red[8];
    __shared__ float s_amax[4];
    __shared__ float s_inv[4];

    int n = blockIdx.x;
    int t = threadIdx.x;
    int beg = g_rowptr[n];
    int deg = g_rowptr[n+1] - beg;
    if (deg > CAP) deg = CAP;   // safety; never triggers for this data

    for (int j = t; j < deg; j += 256) s_eid[j] = g_csr[beg + j];
    __syncthreads();
    if (t == 0) {               // deterministic order: sort tiny list (avg deg ~17)
        for (int i = 1; i < deg; i++) {
            int key = s_eid[i]; int j = i-1;
            while (j >= 0 && s_eid[j] > key) { s_eid[j+1] = s_eid[j]; j--; }
            s_eid[j+1] = key;
        }
    }
    __syncthreads();
    for (int j = t; j < deg; j += 256) {
        int eid = s_eid[j];
        s_src[j] = (eid < EE) ? ei[eid] : (eid - EE);
        float4 a4 = ((const float4*)g_alpha)[eid];
        s_a[j*4+0] = a4.x; s_a[j*4+1] = a4.y; s_a[j*4+2] = a4.z; s_a[j*4+3] = a4.w;
    }
    __syncthreads();

    int hd = t >> 6, lane = t & 63;
    // max per head
    float m = -FLT_MAX;
    for (int j = lane; j < deg; j += 64) m = fmaxf(m, s_a[j*4 + hd]);
    #pragma unroll
    for (int o = 16; o; o >>= 1) m = fmaxf(m, __shfl_xor_sync(0xffffffffu, m, o));
    if ((t & 31) == 0) s_red[t >> 5] = m;
    __syncthreads();
    if (t < 4) s_amax[t] = fmaxf(s_red[2*t], s_red[2*t+1]);
    __syncthreads();
    // exp + sum (store exp back into s_a; fixed lane order -> deterministic)
    float am = s_amax[hd];
    float sum = 0.f;
    for (int j = lane; j < deg; j += 64) {
        float ev = expf(s_a[j*4 + hd] - am);
        s_a[j*4 + hd] = ev;
        sum += ev;
    }
    #pragma unroll
    for (int o = 16; o; o >>= 1) sum += __shfl_xor_sync(0xffffffffu, sum, o);
    if ((t & 31) == 0) s_red[t >> 5] = sum;
    __syncthreads();
    if (t < 4) s_inv[t] = 1.f / ((s_red[2*t] + s_red[2*t+1]) + 1e-16f);
    __syncthreads();
    // normalize coefficients
    for (int j = t; j < deg; j += 256) {
        s_a[j*4+0] *= s_inv[0]; s_a[j*4+1] *= s_inv[1];
        s_a[j*4+2] *= s_inv[2]; s_a[j*4+3] *= s_inv[3];
    }
    __syncthreads();
    // weighted aggregation: thread t owns channel t (head = t>>6)
    float acc = 0.f;
    for (int j = 0; j < deg; j++) {
        float coef = s_a[j*4 + hd];
        int src = s_src[j];
        acc += coef * g_h[(size_t)src*HC + t];
    }
    outp[(size_t)n*HC + t] = acc + bias[t];
}

// ---------------- BatchNorm (deterministic two-stage) ----------------
__global__ void k_bnstats(const float* __restrict__ o) {
    int t = threadIdx.x, b = blockIdx.x;   // 200 blocks x 250 rows
    float s1 = 0.f, s2 = 0.f;
    const float* p = o + (size_t)b*250*HC + t;
    for (int r = 0; r < 250; r++) {
        float v = p[(size_t)r*HC];
        s1 += v; s2 += v*v;
    }
    g_ps1[b*HC + t] = s1;
    g_ps2[b*HC + t] = s2;
}

__global__ void k_bnfin(const float* __restrict__ gamma, const float* __restrict__ beta) {
    int t = threadIdx.x;
    float s1 = 0.f, s2 = 0.f;
    for (int b = 0; b < 200; b++) { s1 += g_ps1[b*HC + t]; s2 += g_ps2[b*HC + t]; }
    float mu  = s1 * (1.0f/NN);
    float var = s2 * (1.0f/NN) - mu*mu;
    float sc  = gamma[t] * rsqrtf(var + BNEPS);
    g_scale[t] = sc;
    g_shift[t] = beta[t] - mu*sc;
}

__global__ void k_bnapply(const float* __restrict__ o, float* __restrict__ x) {
    int t = threadIdx.x;
    size_t i = (size_t)blockIdx.x*HC + t;
    float v = o[i]*g_scale[t] + g_shift[t];
    x[i] = fmaxf(v, 0.f);
}

// ---------------- global mean pool (batch is sorted) ----------------
__global__ void k_pool(const float* __restrict__ x, const int* __restrict__ batch,
                       float* __restrict__ out) {
    __shared__ int s_lo, s_hi;
    int g = blockIdx.x, t = threadIdx.x;
    if (t == 0) {
        int lo = 0, hi = NN;
        while (lo < hi) { int m = (lo+hi) >> 1; if (batch[m] < g) lo = m+1; else hi = m; }
        s_lo = lo;
    }
    if (t == 1) {
        int lo = 0, hi = NN;
        while (lo < hi) { int m = (lo+hi) >> 1; if (batch[m] < g+1) lo = m+1; else hi = m; }
        s_hi = lo;
    }
    __syncthreads();
    float s = 0.f;
    for (int n = s_lo; n < s_hi; n++) s += x[(size_t)n*HC + t];
    int c = s_hi - s_lo;
    out[g*HC + t] = s / (float)max(c, 1);
}

// ---------------- launch ----------------
extern "C" void kernel_launch(void* const* d_in, const int* in_sizes, int n_in,
                              void* d_out, int out_size) {
    const float* x     = (const float*)d_in[0];
    const int*   ei    = (const int*)  d_in[1];
    const float* ea    = (const float*)d_in[2];
    const int*   batch = (const int*)  d_in[3];
    const float* W[3]    = {(const float*)d_in[4],  (const float*)d_in[10], (const float*)d_in[16]};
    const float* aS[3]   = {(const float*)d_in[5],  (const float*)d_in[11], (const float*)d_in[17]};
    const float* aD[3]   = {(const float*)d_in[6],  (const float*)d_in[12], (const float*)d_in[18]};
    const float* bias[3] = {(const float*)d_in[7],  (const float*)d_in[13], (const float*)d_in[19]};
    const float* gam[3]  = {(const float*)d_in[8],  (const float*)d_in[14], (const float*)d_in[20]};
    const float* bet[3]  = {(const float*)d_in[9],  (const float*)d_in[15], (const float*)d_in[21]};
    const float* We0  = (const float*)d_in[22];
    const float* atte = (const float*)d_in[23];
    float* out = (float*)d_out;

    void* p;
    float *hb, *t0, *t1;
    cudaGetSymbolAddress(&p, g_h);  hb = (float*)p;
    cudaGetSymbolAddress(&p, g_t0); t0 = (float*)p;
    cudaGetSymbolAddress(&p, g_t1); t1 = (float*)p;

    int egrid = (ET + 255) / 256;

    k_zero<<<NBLK_SCAN, 256>>>();
    k_edge_mean<<<256, 256>>>(ea);
    k_ve<<<1, 64>>>(We0, atte);
    k_count<<<egrid, 256>>>(ei);
    k_scan1<<<NBLK_SCAN, 256>>>();
    k_scan2<<<1, 256>>>();
    k_scan3<<<NBLK_SCAN, 256>>>();
    k_scatter<<<egrid, 256>>>(ei);

    const float* xin = x;
    int K = 128;
    float* outs[3] = {t0, t0, t1};
    float* xs[3]   = {t1, t0, t1};
    for (int l = 0; l < 3; l++) {
        dim3 gg((NN + 127) / 128, 4);
        k_gemm<<<gg, 256>>>(xin, W[l], hb, NN, K);
        k_nodealpha<<<NN, 128>>>(aS[l], aD[l]);
        k_edgealpha<<<egrid, 256>>>(ei, ea, (l == 0) ? 1 : 0);
        k_aggregate<<<NN, 256>>>(ei, bias[l], outs[l]);
        k_bnstats<<<200, 256>>>(outs[l]);
        k_bnfin<<<1, 256>>>(gam[l], bet[l]);
        k_bnapply<<<NN, 256>>>(outs[l], xs[l]);
        xin = xs[l];
        K = HC;
    }
    k_pool<<<GG, 256>>>(xin, batch, out);
}

// round 7
// speedup vs baseline: 1.1937x; 1.1937x over previous
#include <cuda_runtime.h>
#include <cuda_bf16.h>
#include <math.h>
#include <float.h>
#include <stdint.h>

// Problem constants
#define NN 50000
#define EE 800000
#define ET (EE+NN)
#define HH 4
#define HC 256
#define GG 256
#define EDIM 16
#define NEG 0.2f
#define BNEPS 1e-5f
#define CAP 1024
#define NBLK_SCAN 196

// ---------------- device scratch ----------------
__device__ float g_h [(size_t)NN*HC];
__device__ float g_t0[(size_t)NN*HC];
__device__ float g_t1[(size_t)NN*HC];
__device__ __nv_bfloat16 g_xs[(size_t)NN*512];   // split input  [M][2K] (hi|lo)
__device__ __nv_bfloat16 g_ws[256*512];          // split weight [N][2K] (hi|lo), N-major
__device__ float g_alpha[(size_t)ET*HH];
__device__ float g_asrc[NN*HH];
__device__ float g_adst[NN*HH];
__device__ int   g_deg[NN];
__device__ int   g_rowptr[NN+1];
__device__ int   g_cursor[NN];
__device__ int   g_csr[ET];
__device__ int   g_bsum[256];
__device__ float g_ps1[200*HC];
__device__ float g_ps2[200*HC];
__device__ float g_scale[HC];
__device__ float g_shift[HC];
__device__ float g_ve[EDIM*HH];
__device__ float g_sl[HH];
__device__ float g_mpart[256*EDIM];

// ---------------- PTX helpers (sm_80-level; compile at plain sm_103) ----------------
__device__ __forceinline__ uint32_t smem_u32(const void* p) {
    uint32_t a;
    asm("{ .reg .u64 t; cvta.to.shared.u64 t, %1; cvt.u32.u64 %0, t; }" : "=r"(a) : "l"(p));
    return a;
}
__device__ __forceinline__ void ldsm4(uint32_t& r0, uint32_t& r1, uint32_t& r2, uint32_t& r3, uint32_t a) {
    asm volatile("ldmatrix.sync.aligned.m8n8.x4.shared.b16 {%0,%1,%2,%3}, [%4];"
                 : "=r"(r0), "=r"(r1), "=r"(r2), "=r"(r3) : "r"(a));
}
__device__ __forceinline__ void mma16816(float* c, const uint32_t* a, const uint32_t* b) {
    asm volatile("mma.sync.aligned.m16n8k16.row.col.f32.bf16.bf16.f32 "
                 "{%0,%1,%2,%3}, {%4,%5,%6,%7}, {%8,%9}, {%0,%1,%2,%3};"
                 : "+f"(c[0]), "+f"(c[1]), "+f"(c[2]), "+f"(c[3])
                 : "r"(a[0]), "r"(a[1]), "r"(a[2]), "r"(a[3]), "r"(b[0]), "r"(b[1]));
}
__device__ __forceinline__ void cpa16(uint32_t dst, const void* src, int sz) {
    asm volatile("cp.async.cg.shared.global [%0], [%1], 16, %2;" :: "r"(dst), "l"(src), "r"(sz));
}

// ================= HMMA bf16-split GEMM =================
// C[M,256] = A2[M,K2] @ B2[256,K2]^T   (A2,B2 bf16 hi|lo concatenation)
// Block tile 128x128 (grid.y = 2 halves of N=256), 8 warps (2m x 4n), warp 64x32.
#define KC 32
#define PITCH 80
#define ABUF 10240
#define BUFSZ 20480

__global__ void __launch_bounds__(256, 2) k_gemm_hmma(
    const __nv_bfloat16* __restrict__ A, const __nv_bfloat16* __restrict__ B,
    float* __restrict__ C, int M, int K2)
{
    __shared__ __align__(16) unsigned char sm[2*BUFSZ];
    int tid = threadIdx.x, lane = tid & 31, wid = tid >> 5;
    int wm = wid & 1, wn = wid >> 1;
    int row0 = blockIdx.x * 128;
    int ncol0 = blockIdx.y * 128;
    uint32_t sb = smem_u32(sm);

    float acc[4][4][4];
    #pragma unroll
    for (int i = 0; i < 4; i++)
        #pragma unroll
        for (int j = 0; j < 4; j++)
            { acc[i][j][0]=0.f; acc[i][j][1]=0.f; acc[i][j][2]=0.f; acc[i][j][3]=0.f; }

    int nc = K2 / KC;
    int r = tid >> 2, seg = tid & 3;

    // prefetch chunk 0
    {
        uint32_t ab = sb, bb = sb + ABUF;
        #pragma unroll
        for (int i = 0; i < 2; i++) {
            int rr = r + i*64;
            int grow = row0 + rr;
            const __nv_bfloat16* srcA = A + (size_t)((grow < M) ? grow : 0)*K2 + seg*8;
            cpa16(ab + rr*PITCH + seg*16, srcA, (grow < M) ? 16 : 0);
            const __nv_bfloat16* srcB = B + (size_t)(ncol0 + rr)*K2 + seg*8;
            cpa16(bb + rr*PITCH + seg*16, srcB, 16);
        }
        asm volatile("cp.async.commit_group;");
    }

    for (int c = 0; c < nc; c++) {
        if (c + 1 < nc) {
            int k0 = (c+1)*KC, buf = (c+1) & 1;
            uint32_t ab = sb + buf*BUFSZ, bb = ab + ABUF;
            #pragma unroll
            for (int i = 0; i < 2; i++) {
                int rr = r + i*64;
                int grow = row0 + rr;
                const __nv_bfloat16* srcA = A + (size_t)((grow < M) ? grow : 0)*K2 + k0 + seg*8;
                cpa16(ab + rr*PITCH + seg*16, srcA, (grow < M) ? 16 : 0);
                const __nv_bfloat16* srcB = B + (size_t)(ncol0 + rr)*K2 + k0 + seg*8;
                cpa16(bb + rr*PITCH + seg*16, srcB, 16);
            }
            asm volatile("cp.async.commit_group;");
            asm volatile("cp.async.wait_group 1;");
        } else {
            asm volatile("cp.async.wait_group 0;");
        }
        __syncthreads();

        int buf = c & 1;
        uint32_t ab = sb + buf*BUFSZ, bb = ab + ABUF;
        #pragma unroll
        for (int ks = 0; ks < 2; ks++) {
            int k = ks * 16;
            uint32_t afr[4][4];
            #pragma unroll
            for (int mt = 0; mt < 4; mt++) {
                uint32_t addr = ab + (wm*64 + mt*16 + (lane & 15))*PITCH + (k + 8*(lane >> 4))*2;
                ldsm4(afr[mt][0], afr[mt][1], afr[mt][2], afr[mt][3], addr);
            }
            uint32_t bfr[4][2];
            #pragma unroll
            for (int np = 0; np < 2; np++) {
                int ntA = np*2;
                int quad = lane >> 3, l8 = lane & 7;
                int nrow = wn*32 + (ntA + (quad >> 1))*8 + l8;
                int kk = k + 8*(quad & 1);
                uint32_t addr = bb + nrow*PITCH + kk*2;
                ldsm4(bfr[ntA][0], bfr[ntA][1], bfr[ntA+1][0], bfr[ntA+1][1], addr);
            }
            #pragma unroll
            for (int mt = 0; mt < 4; mt++)
                #pragma unroll
                for (int nt = 0; nt < 4; nt++)
                    mma16816(acc[mt][nt], afr[mt], bfr[nt]);
        }
        __syncthreads();
    }

    // epilogue
    int g = lane >> 2, tig = lane & 3;
    #pragma unroll
    for (int mt = 0; mt < 4; mt++) {
        int rowa = row0 + wm*64 + mt*16 + g;
        #pragma unroll
        for (int nt = 0; nt < 4; nt++) {
            int col = ncol0 + wn*32 + nt*8 + tig*2;
            if (rowa < M)
                *(float2*)(C + (size_t)rowa*HC + col) = make_float2(acc[mt][nt][0], acc[mt][nt][1]);
            if (rowa + 8 < M)
                *(float2*)(C + (size_t)(rowa+8)*HC + col) = make_float2(acc[mt][nt][2], acc[mt][nt][3]);
        }
    }
}

// ---------------- bf16-split conversions ----------------
// layer0 input: x f32 [M][128] -> g_xs rows of 256 (hi|lo)
__global__ void k_cvtX(const float* __restrict__ x) {
    int i = blockIdx.x*256 + threadIdx.x;
    if (i >= NN*128) return;
    int row = i >> 7, k = i & 127;
    float v = x[i];
    __nv_bfloat16 hi = __float2bfloat16_rn(v);
    g_xs[(size_t)row*256 + k] = hi;
    g_xs[(size_t)row*256 + 128 + k] = __float2bfloat16_rn(v - __bfloat162float(hi));
}

// weight W [K][256] -> g_ws [n][2K] (hi|lo)
__global__ void k_cvtW(const float* __restrict__ W, int K) {
    int n = blockIdx.x, k = threadIdx.x;
    if (k >= K) return;
    float v = W[(size_t)k*HC + n];
    __nv_bfloat16 hi = __float2bfloat16_rn(v);
    g_ws[n*(2*K) + k] = hi;
    g_ws[n*(2*K) + K + k] = __float2bfloat16_rn(v - __bfloat162float(hi));
}

// ---------------- small init ----------------
__global__ void k_zero() {
    int i = blockIdx.x*256 + threadIdx.x;
    if (i < NN) g_deg[i] = 0;
}

// ---------------- edge_attr mean ----------------
__global__ void k_edge_mean(const float* __restrict__ ea) {
    __shared__ float smv[256];
    int t = threadIdx.x;
    int col = t & 15, rr = t >> 4;
    int b = blockIdx.x;
    float s = 0.f;
    const float* base = ea + (size_t)b*3125*EDIM;
    for (int row = rr; row < 3125; row += 16)
        s += base[row*EDIM + col];
    smv[t] = s; __syncthreads();
    if (t < EDIM) {
        float tot = 0.f;
        #pragma unroll
        for (int q = 0; q < 16; q++) tot += smv[q*16 + t];
        g_mpart[b*EDIM + t] = tot;
    }
}

__global__ void k_ve(const float* __restrict__ We0, const float* __restrict__ atte) {
    __shared__ float s_mean[EDIM];
    __shared__ float s_ve[EDIM*HH];
    int t = threadIdx.x;
    if (t < EDIM) {
        float s = 0.f;
        for (int b = 0; b < 256; b++) s += g_mpart[b*EDIM + t];
        s_mean[t] = s * (1.0f/EE);
    }
    {
        int d = t >> 2, hd = t & 3;
        float s = 0.f;
        for (int c = 0; c < 64; c++)
            s += We0[d*HC + hd*64 + c] * atte[hd*64 + c];
        s_ve[t] = s; g_ve[t] = s;
    }
    __syncthreads();
    if (t < HH) {
        float s = 0.f;
        for (int d = 0; d < EDIM; d++) s += s_mean[d] * s_ve[d*4 + t];
        g_sl[t] = s;
    }
}

// ---------------- CSR build ----------------
__global__ void k_count(const int* __restrict__ ei) {
    int e = blockIdx.x*256 + threadIdx.x;
    if (e >= ET) return;
    int d = (e < EE) ? ei[EE + e] : (e - EE);
    atomicAdd(&g_deg[d], 1);
}

__global__ void k_scan1() {
    __shared__ int smv[256];
    int t = threadIdx.x, i = blockIdx.x*256 + t;
    int v = (i < NN) ? g_deg[i] : 0;
    smv[t] = v; __syncthreads();
    for (int o = 1; o < 256; o <<= 1) {
        int x = (t >= o) ? smv[t-o] : 0;
        __syncthreads();
        smv[t] += x;
        __syncthreads();
    }
    if (i < NN) g_rowptr[i] = smv[t] - v;
    if (t == 255) g_bsum[blockIdx.x] = smv[255];
}

__global__ void k_scan2() {
    __shared__ int smv[256];
    int t = threadIdx.x;
    int v = (t < NBLK_SCAN) ? g_bsum[t] : 0;
    smv[t] = v; __syncthreads();
    for (int o = 1; o < 256; o <<= 1) {
        int x = (t >= o) ? smv[t-o] : 0;
        __syncthreads();
        smv[t] += x;
        __syncthreads();
    }
    g_bsum[t] = smv[t] - v;
}

__global__ void k_scan3() {
    int t = threadIdx.x, i = blockIdx.x*256 + t;
    if (i < NN) {
        int rp = g_rowptr[i] + g_bsum[blockIdx.x];
        g_rowptr[i] = rp;
        g_cursor[i] = rp;
    }
    if (i == 0) g_rowptr[NN] = ET;
}

__global__ void k_scatter(const int* __restrict__ ei) {
    int e = blockIdx.x*256 + threadIdx.x;
    if (e >= ET) return;
    int d = (e < EE) ? ei[EE + e] : (e - EE);
    int pos = atomicAdd(&g_cursor[d], 1);
    g_csr[pos] = e;
}

// ---------------- per-node attention dot products ----------------
__global__ void k_nodealpha(const float* __restrict__ aS, const float* __restrict__ aD) {
    int n = blockIdx.x;
    int w = threadIdx.x >> 5, lane = threadIdx.x & 31;
    const float* hp = g_h + (size_t)n*HC + w*64;
    float v1 = hp[lane], v2 = hp[lane+32];
    float s = v1*aS[w*64+lane] + v2*aS[w*64+lane+32];
    float d = v1*aD[w*64+lane] + v2*aD[w*64+lane+32];
    #pragma unroll
    for (int o = 16; o; o >>= 1) {
        s += __shfl_xor_sync(0xffffffffu, s, o);
        d += __shfl_xor_sync(0xffffffffu, d, o);
    }
    if (lane == 0) { g_asrc[n*4+w] = s; g_adst[n*4+w] = d; }
}

// ---------------- per-edge alpha ----------------
__global__ void k_edgealpha(const int* __restrict__ ei, const float* __restrict__ ea, int l0) {
    int e = blockIdx.x*256 + threadIdx.x;
    if (e >= ET) return;
    int s, d;
    if (e < EE) { s = ei[e]; d = ei[EE + e]; } else { s = d = e - EE; }
    float4 a = ((const float4*)g_asrc)[s];
    float4 b = ((const float4*)g_adst)[d];
    float al[4] = {a.x+b.x, a.y+b.y, a.z+b.z, a.w+b.w};
    if (l0) {
        if (e < EE) {
            const float* er = ea + (size_t)e*EDIM;
            float ex0=0.f, ex1=0.f, ex2=0.f, ex3=0.f;
            #pragma unroll
            for (int k = 0; k < EDIM; k++) {
                float v = er[k];
                ex0 += v*g_ve[k*4+0]; ex1 += v*g_ve[k*4+1];
                ex2 += v*g_ve[k*4+2]; ex3 += v*g_ve[k*4+3];
            }
            al[0]+=ex0; al[1]+=ex1; al[2]+=ex2; al[3]+=ex3;
        } else {
            al[0]+=g_sl[0]; al[1]+=g_sl[1]; al[2]+=g_sl[2]; al[3]+=g_sl[3];
        }
    }
    #pragma unroll
    for (int i = 0; i < 4; i++) al[i] = (al[i] >= 0.f) ? al[i] : NEG*al[i];
    ((float4*)g_alpha)[e] = make_float4(al[0], al[1], al[2], al[3]);
}

// ---------------- per-dst aggregation ----------------
__global__ void __launch_bounds__(256) k_aggregate(const int* __restrict__ ei,
                                                   const float* __restrict__ bias,
                                                   float* __restrict__ outp) {
    __shared__ int   s_eid[CAP];
    __shared__ int   s_src[CAP];
    __shared__ float s_a[CAP*4];
    __shared__ float s_red[8];
    __shared__ float s_amax[4];
    __shared__ float s_inv[4];

    int n = blockIdx.x;
    int t = threadIdx.x;
    int beg = g_rowptr[n];
    int deg = g_rowptr[n+1] - beg;
    if (deg > CAP) deg = CAP;

    for (int j = t; j < deg; j += 256) s_eid[j] = g_csr[beg + j];
    __syncthreads();
    if (t == 0) {
        for (int i = 1; i < deg; i++) {
            int key = s_eid[i]; int j = i-1;
            while (j >= 0 && s_eid[j] > key) { s_eid[j+1] = s_eid[j]; j--; }
            s_eid[j+1] = key;
        }
    }
    __syncthreads();
    for (int j = t; j < deg; j += 256) {
        int eid = s_eid[j];
        s_src[j] = (eid < EE) ? ei[eid] : (eid - EE);
        float4 a4 = ((const float4*)g_alpha)[eid];
        s_a[j*4+0] = a4.x; s_a[j*4+1] = a4.y; s_a[j*4+2] = a4.z; s_a[j*4+3] = a4.w;
    }
    __syncthreads();

    int hd = t >> 6, lane = t & 63;
    float m = -FLT_MAX;
    for (int j = lane; j < deg; j += 64) m = fmaxf(m, s_a[j*4 + hd]);
    #pragma unroll
    for (int o = 16; o; o >>= 1) m = fmaxf(m, __shfl_xor_sync(0xffffffffu, m, o));
    if ((t & 31) == 0) s_red[t >> 5] = m;
    __syncthreads();
    if (t < 4) s_amax[t] = fmaxf(s_red[2*t], s_red[2*t+1]);
    __syncthreads();
    float am = s_amax[hd];
    float sum = 0.f;
    for (int j = lane; j < deg; j += 64) {
        float ev = expf(s_a[j*4 + hd] - am);
        s_a[j*4 + hd] = ev;
        sum += ev;
    }
    #pragma unroll
    for (int o = 16; o; o >>= 1) sum += __shfl_xor_sync(0xffffffffu, sum, o);
    if ((t & 31) == 0) s_red[t >> 5] = sum;
    __syncthreads();
    if (t < 4) s_inv[t] = 1.f / ((s_red[2*t] + s_red[2*t+1]) + 1e-16f);
    __syncthreads();
    for (int j = t; j < deg; j += 256) {
        s_a[j*4+0] *= s_inv[0]; s_a[j*4+1] *= s_inv[1];
        s_a[j*4+2] *= s_inv[2]; s_a[j*4+3] *= s_inv[3];
    }
    __syncthreads();
    float acc = 0.f;
    for (int j = 0; j < deg; j++) {
        float coef = s_a[j*4 + hd];
        int src = s_src[j];
        acc += coef * g_h[(size_t)src*HC + t];
    }
    outp[(size_t)n*HC + t] = acc + bias[t];
}

// ---------------- BatchNorm ----------------
__global__ void k_bnstats(const float* __restrict__ o) {
    int t = threadIdx.x, b = blockIdx.x;
    float s1 = 0.f, s2 = 0.f;
    const float* p = o + (size_t)b*250*HC + t;
    for (int rr = 0; rr < 250; rr++) {
        float v = p[(size_t)rr*HC];
        s1 += v; s2 += v*v;
    }
    g_ps1[b*HC + t] = s1;
    g_ps2[b*HC + t] = s2;
}

__global__ void k_bnfin(const float* __restrict__ gamma, const float* __restrict__ beta) {
    int t = threadIdx.x;
    float s1 = 0.f, s2 = 0.f;
    for (int b = 0; b < 200; b++) { s1 += g_ps1[b*HC + t]; s2 += g_ps2[b*HC + t]; }
    float mu  = s1 * (1.0f/NN);
    float var = s2 * (1.0f/NN) - mu*mu;
    float sc  = gamma[t] * rsqrtf(var + BNEPS);
    g_scale[t] = sc;
    g_shift[t] = beta[t] - mu*sc;
}

// BN apply + ReLU + bf16 split -> g_xs [M][512]
__global__ void k_bnapply_bf16(const float* __restrict__ o) {
    int t = threadIdx.x;
    size_t i = (size_t)blockIdx.x*HC + t;
    float v = fmaxf(o[i]*g_scale[t] + g_shift[t], 0.f);
    __nv_bfloat16 hi = __float2bfloat16_rn(v);
    g_xs[(size_t)blockIdx.x*512 + t] = hi;
    g_xs[(size_t)blockIdx.x*512 + 256 + t] = __float2bfloat16_rn(v - __bfloat162float(hi));
}

// BN apply + ReLU -> f32 (last layer, feeds pool)
__global__ void k_bnapply_f32(const float* __restrict__ o, float* __restrict__ x) {
    int t = threadIdx.x;
    size_t i = (size_t)blockIdx.x*HC + t;
    float v = o[i]*g_scale[t] + g_shift[t];
    x[i] = fmaxf(v, 0.f);
}

// ---------------- global mean pool ----------------
__global__ void k_pool(const float* __restrict__ x, const int* __restrict__ batch,
                       float* __restrict__ out) {
    __shared__ int s_lo, s_hi;
    int g = blockIdx.x, t = threadIdx.x;
    if (t == 0) {
        int lo = 0, hi = NN;
        while (lo < hi) { int m = (lo+hi) >> 1; if (batch[m] < g) lo = m+1; else hi = m; }
        s_lo = lo;
    }
    if (t == 1) {
        int lo = 0, hi = NN;
        while (lo < hi) { int m = (lo+hi) >> 1; if (batch[m] < g+1) lo = m+1; else hi = m; }
        s_hi = lo;
    }
    __syncthreads();
    float s = 0.f;
    for (int n = s_lo; n < s_hi; n++) s += x[(size_t)n*HC + t];
    int c = s_hi - s_lo;
    out[g*HC + t] = s / (float)max(c, 1);
}

// ---------------- launch ----------------
extern "C" void kernel_launch(void* const* d_in, const int* in_sizes, int n_in,
                              void* d_out, int out_size) {
    const float* x     = (const float*)d_in[0];
    const int*   ei    = (const int*)  d_in[1];
    const float* ea    = (const float*)d_in[2];
    const int*   batch = (const int*)  d_in[3];
    const float* W[3]    = {(const float*)d_in[4],  (const float*)d_in[10], (const float*)d_in[16]};
    const float* aS[3]   = {(const float*)d_in[5],  (const float*)d_in[11], (const float*)d_in[17]};
    const float* aD[3]   = {(const float*)d_in[6],  (const float*)d_in[12], (const float*)d_in[18]};
    const float* bias[3] = {(const float*)d_in[7],  (const float*)d_in[13], (const float*)d_in[19]};
    const float* gam[3]  = {(const float*)d_in[8],  (const float*)d_in[14], (const float*)d_in[20]};
    const float* bet[3]  = {(const float*)d_in[9],  (const float*)d_in[15], (const float*)d_in[21]};
    const float* We0  = (const float*)d_in[22];
    const float* atte = (const float*)d_in[23];
    float* out = (float*)d_out;

    void* p;
    float *hb, *t0, *t1;
    __nv_bfloat16 *xs, *ws;
    cudaGetSymbolAddress(&p, g_h);  hb = (float*)p;
    cudaGetSymbolAddress(&p, g_t0); t0 = (float*)p;
    cudaGetSymbolAddress(&p, g_t1); t1 = (float*)p;
    cudaGetSymbolAddress(&p, g_xs); xs = (__nv_bfloat16*)p;
    cudaGetSymbolAddress(&p, g_ws); ws = (__nv_bfloat16*)p;

    int egrid = (ET + 255) / 256;
    int gtiles = (NN + 127) / 128;

    k_zero<<<NBLK_SCAN, 256>>>();
    k_edge_mean<<<256, 256>>>(ea);
    k_ve<<<1, 64>>>(We0, atte);
    k_count<<<egrid, 256>>>(ei);
    k_scan1<<<NBLK_SCAN, 256>>>();
    k_scan2<<<1, 256>>>();
    k_scan3<<<NBLK_SCAN, 256>>>();
    k_scatter<<<egrid, 256>>>(ei);

    k_cvtX<<<(NN*128 + 255)/256, 256>>>(x);

    int K = 128;
    for (int l = 0; l < 3; l++) {
        k_cvtW<<<HC, K>>>(W[l], K);
        k_gemm_hmma<<<dim3(gtiles, 2), 256>>>(xs, ws, hb, NN, 2*K);
        k_nodealpha<<<NN, 128>>>(aS[l], aD[l]);
        k_edgealpha<<<egrid, 256>>>(ei, ea, (l == 0) ? 1 : 0);
        k_aggregate<<<NN, 256>>>(ei, bias[l], t0);
        k_bnstats<<<200, 256>>>(t0);
        k_bnfin<<<1, 256>>>(gam[l], bet[l]);
        if (l < 2) k_bnapply_bf16<<<NN, 256>>>(t0);
        else       k_bnapply_f32<<<NN, 256>>>(t0, t1);
        K = HC;
    }
    k_pool<<<GG, 256>>>(t1, batch, out);
}

// round 8
// speedup vs baseline: 1.3398x; 1.1223x over previous
#include <cuda_runtime.h>
#include <cuda_bf16.h>
#include <math.h>
#include <float.h>
#include <stdint.h>

// Problem constants
#define NN 50000
#define EE 800000
#define ET (EE+NN)
#define HH 4
#define HC 256
#define GG 256
#define EDIM 16
#define NEG 0.2f
#define BNEPS 1e-5f
#define CAP 1024
#define NBLK_SCAN 196

// ---------------- device scratch ----------------
__device__ float g_h [(size_t)NN*HC];
__device__ float g_t0[(size_t)NN*HC];
__device__ __nv_bfloat16 g_xs[(size_t)NN*512];   // split input  [M][2K] (hi|lo)
__device__ __nv_bfloat16 g_ws[256*512];          // split weight [N][2K] (hi|lo), N-major
__device__ float g_aec[(size_t)ET*HH];           // layer-0 edge-attr alpha, CSR order
__device__ float g_asrc[NN*HH];
__device__ float g_adst[NN*HH];
__device__ int   g_deg[NN];
__device__ int   g_rowptr[NN+1];
__device__ int   g_cursor[NN];
__device__ int   g_csr[ET];                      // eids (atomic order; consumed by sortcsr)
__device__ int   g_srcs[ET];                     // src node ids, sorted CSR order
__device__ int   g_bsum[256];
__device__ float g_ps1[200*HC];
__device__ float g_ps2[200*HC];
__device__ float g_scale[HC];
__device__ float g_shift[HC];
__device__ float g_ve[EDIM*HH];
__device__ float g_sl[HH];
__device__ float g_mpart[256*EDIM];

// ---------------- PTX helpers ----------------
__device__ __forceinline__ uint32_t smem_u32(const void* p) {
    uint32_t a;
    asm("{ .reg .u64 t; cvta.to.shared.u64 t, %1; cvt.u32.u64 %0, t; }" : "=r"(a) : "l"(p));
    return a;
}
__device__ __forceinline__ void ldsm4(uint32_t& r0, uint32_t& r1, uint32_t& r2, uint32_t& r3, uint32_t a) {
    asm volatile("ldmatrix.sync.aligned.m8n8.x4.shared.b16 {%0,%1,%2,%3}, [%4];"
                 : "=r"(r0), "=r"(r1), "=r"(r2), "=r"(r3) : "r"(a));
}
__device__ __forceinline__ void mma16816(float* c, const uint32_t* a, const uint32_t* b) {
    asm volatile("mma.sync.aligned.m16n8k16.row.col.f32.bf16.bf16.f32 "
                 "{%0,%1,%2,%3}, {%4,%5,%6,%7}, {%8,%9}, {%0,%1,%2,%3};"
                 : "+f"(c[0]), "+f"(c[1]), "+f"(c[2]), "+f"(c[3])
                 : "r"(a[0]), "r"(a[1]), "r"(a[2]), "r"(a[3]), "r"(b[0]), "r"(b[1]));
}
__device__ __forceinline__ void cpa16(uint32_t dst, const void* src, int sz) {
    asm volatile("cp.async.cg.shared.global [%0], [%1], 16, %2;" :: "r"(dst), "l"(src), "r"(sz));
}

// ================= HMMA bf16-split GEMM (unchanged, validated R6) =================
#define KC 32
#define PITCH 80
#define ABUF 10240
#define BUFSZ 20480

__global__ void __launch_bounds__(256, 2) k_gemm_hmma(
    const __nv_bfloat16* __restrict__ A, const __nv_bfloat16* __restrict__ B,
    float* __restrict__ C, int M, int K2)
{
    __shared__ __align__(16) unsigned char sm[2*BUFSZ];
    int tid = threadIdx.x, lane = tid & 31, wid = tid >> 5;
    int wm = wid & 1, wn = wid >> 1;
    int row0 = blockIdx.x * 128;
    int ncol0 = blockIdx.y * 128;
    uint32_t sb = smem_u32(sm);

    float acc[4][4][4];
    #pragma unroll
    for (int i = 0; i < 4; i++)
        #pragma unroll
        for (int j = 0; j < 4; j++)
            { acc[i][j][0]=0.f; acc[i][j][1]=0.f; acc[i][j][2]=0.f; acc[i][j][3]=0.f; }

    int nc = K2 / KC;
    int r = tid >> 2, seg = tid & 3;

    {
        uint32_t ab = sb, bb = sb + ABUF;
        #pragma unroll
        for (int i = 0; i < 2; i++) {
            int rr = r + i*64;
            int grow = row0 + rr;
            const __nv_bfloat16* srcA = A + (size_t)((grow < M) ? grow : 0)*K2 + seg*8;
            cpa16(ab + rr*PITCH + seg*16, srcA, (grow < M) ? 16 : 0);
            const __nv_bfloat16* srcB = B + (size_t)(ncol0 + rr)*K2 + seg*8;
            cpa16(bb + rr*PITCH + seg*16, srcB, 16);
        }
        asm volatile("cp.async.commit_group;");
    }

    for (int c = 0; c < nc; c++) {
        if (c + 1 < nc) {
            int k0 = (c+1)*KC, buf = (c+1) & 1;
            uint32_t ab = sb + buf*BUFSZ, bb = ab + ABUF;
            #pragma unroll
            for (int i = 0; i < 2; i++) {
                int rr = r + i*64;
                int grow = row0 + rr;
                const __nv_bfloat16* srcA = A + (size_t)((grow < M) ? grow : 0)*K2 + k0 + seg*8;
                cpa16(ab + rr*PITCH + seg*16, srcA, (grow < M) ? 16 : 0);
                const __nv_bfloat16* srcB = B + (size_t)(ncol0 + rr)*K2 + k0 + seg*8;
                cpa16(bb + rr*PITCH + seg*16, srcB, 16);
            }
            asm volatile("cp.async.commit_group;");
            asm volatile("cp.async.wait_group 1;");
        } else {
            asm volatile("cp.async.wait_group 0;");
        }
        __syncthreads();

        int buf = c & 1;
        uint32_t ab = sb + buf*BUFSZ, bb = ab + ABUF;
        #pragma unroll
        for (int ks = 0; ks < 2; ks++) {
            int k = ks * 16;
            uint32_t afr[4][4];
            #pragma unroll
            for (int mt = 0; mt < 4; mt++) {
                uint32_t addr = ab + (wm*64 + mt*16 + (lane & 15))*PITCH + (k + 8*(lane >> 4))*2;
                ldsm4(afr[mt][0], afr[mt][1], afr[mt][2], afr[mt][3], addr);
            }
            uint32_t bfr[4][2];
            #pragma unroll
            for (int np = 0; np < 2; np++) {
                int ntA = np*2;
                int quad = lane >> 3, l8 = lane & 7;
                int nrow = wn*32 + (ntA + (quad >> 1))*8 + l8;
                int kk = k + 8*(quad & 1);
                uint32_t addr = bb + nrow*PITCH + kk*2;
                ldsm4(bfr[ntA][0], bfr[ntA][1], bfr[ntA+1][0], bfr[ntA+1][1], addr);
            }
            #pragma unroll
            for (int mt = 0; mt < 4; mt++)
                #pragma unroll
                for (int nt = 0; nt < 4; nt++)
                    mma16816(acc[mt][nt], afr[mt], bfr[nt]);
        }
        __syncthreads();
    }

    int g = lane >> 2, tig = lane & 3;
    #pragma unroll
    for (int mt = 0; mt < 4; mt++) {
        int rowa = row0 + wm*64 + mt*16 + g;
        #pragma unroll
        for (int nt = 0; nt < 4; nt++) {
            int col = ncol0 + wn*32 + nt*8 + tig*2;
            if (rowa < M)
                *(float2*)(C + (size_t)rowa*HC + col) = make_float2(acc[mt][nt][0], acc[mt][nt][1]);
            if (rowa + 8 < M)
                *(float2*)(C + (size_t)(rowa+8)*HC + col) = make_float2(acc[mt][nt][2], acc[mt][nt][3]);
        }
    }
}

// ---------------- bf16-split conversions ----------------
__global__ void k_cvtX(const float* __restrict__ x) {
    int i = blockIdx.x*256 + threadIdx.x;
    if (i >= NN*128) return;
    int row = i >> 7, k = i & 127;
    float v = x[i];
    __nv_bfloat16 hi = __float2bfloat16_rn(v);
    g_xs[(size_t)row*256 + k] = hi;
    g_xs[(size_t)row*256 + 128 + k] = __float2bfloat16_rn(v - __bfloat162float(hi));
}

__global__ void k_cvtW(const float* __restrict__ W, int K) {
    int n = blockIdx.x, k = threadIdx.x;
    if (k >= K) return;
    float v = W[(size_t)k*HC + n];
    __nv_bfloat16 hi = __float2bfloat16_rn(v);
    g_ws[n*(2*K) + k] = hi;
    g_ws[n*(2*K) + K + k] = __float2bfloat16_rn(v - __bfloat162float(hi));
}

// ---------------- small init ----------------
__global__ void k_zero() {
    int i = blockIdx.x*256 + threadIdx.x;
    if (i < NN) g_deg[i] = 0;
}

// ---------------- edge_attr mean ----------------
__global__ void k_edge_mean(const float* __restrict__ ea) {
    __shared__ float smv[256];
    int t = threadIdx.x;
    int col = t & 15, rr = t >> 4;
    int b = blockIdx.x;
    float s = 0.f;
    const float* base = ea + (size_t)b*3125*EDIM;
    for (int row = rr; row < 3125; row += 16)
        s += base[row*EDIM + col];
    smv[t] = s; __syncthreads();
    if (t < EDIM) {
        float tot = 0.f;
        #pragma unroll
        for (int q = 0; q < 16; q++) tot += smv[q*16 + t];
        g_mpart[b*EDIM + t] = tot;
    }
}

__global__ void k_ve(const float* __restrict__ We0, const float* __restrict__ atte) {
    __shared__ float s_mean[EDIM];
    __shared__ float s_ve[EDIM*HH];
    int t = threadIdx.x;
    if (t < EDIM) {
        float s = 0.f;
        for (int b = 0; b < 256; b++) s += g_mpart[b*EDIM + t];
        s_mean[t] = s * (1.0f/EE);
    }
    {
        int d = t >> 2, hd = t & 3;
        float s = 0.f;
        for (int c = 0; c < 64; c++)
            s += We0[d*HC + hd*64 + c] * atte[hd*64 + c];
        s_ve[t] = s; g_ve[t] = s;
    }
    __syncthreads();
    if (t < HH) {
        float s = 0.f;
        for (int d = 0; d < EDIM; d++) s += s_mean[d] * s_ve[d*4 + t];
        g_sl[t] = s;
    }
}

// ---------------- CSR build ----------------
__global__ void k_count(const int* __restrict__ ei) {
    int e = blockIdx.x*256 + threadIdx.x;
    if (e >= ET) return;
    int d = (e < EE) ? ei[EE + e] : (e - EE);
    atomicAdd(&g_deg[d], 1);
}

__global__ void k_scan1() {
    __shared__ int smv[256];
    int t = threadIdx.x, i = blockIdx.x*256 + t;
    int v = (i < NN) ? g_deg[i] : 0;
    smv[t] = v; __syncthreads();
    for (int o = 1; o < 256; o <<= 1) {
        int x = (t >= o) ? smv[t-o] : 0;
        __syncthreads();
        smv[t] += x;
        __syncthreads();
    }
    if (i < NN) g_rowptr[i] = smv[t] - v;
    if (t == 255) g_bsum[blockIdx.x] = smv[255];
}

__global__ void k_scan2() {
    __shared__ int smv[256];
    int t = threadIdx.x;
    int v = (t < NBLK_SCAN) ? g_bsum[t] : 0;
    smv[t] = v; __syncthreads();
    for (int o = 1; o < 256; o <<= 1) {
        int x = (t >= o) ? smv[t-o] : 0;
        __syncthreads();
        smv[t] += x;
        __syncthreads();
    }
    g_bsum[t] = smv[t] - v;
}

__global__ void k_scan3() {
    int t = threadIdx.x, i = blockIdx.x*256 + t;
    if (i < NN) {
        int rp = g_rowptr[i] + g_bsum[blockIdx.x];
        g_rowptr[i] = rp;
        g_cursor[i] = rp;
    }
    if (i == 0) g_rowptr[NN] = ET;
}

__global__ void k_scatter(const int* __restrict__ ei) {
    int e = blockIdx.x*256 + threadIdx.x;
    if (e >= ET) return;
    int d = (e < EE) ? ei[EE + e] : (e - EE);
    int pos = atomicAdd(&g_cursor[d], 1);
    g_csr[pos] = e;
}

// ---------------- CSR canonicalize: rank-sort by eid (deterministic), fill srcs + layer0 edge alpha ----------------
__global__ void __launch_bounds__(128) k_sortcsr(const int* __restrict__ ei,
                                                 const float* __restrict__ ea) {
    __shared__ int s_eid[CAP];
    __shared__ float s_ve[EDIM*HH];
    __shared__ float s_sl[HH];
    int n = blockIdx.x, t = threadIdx.x;
    int beg = g_rowptr[n];
    int deg = g_rowptr[n+1] - beg;
    if (deg > CAP) deg = CAP;

    if (t < EDIM*HH) s_ve[t] = g_ve[t];
    if (t < HH) s_sl[t] = g_sl[t];
    for (int j = t; j < deg; j += 128) s_eid[j] = g_csr[beg + j];
    __syncthreads();

    for (int j = t; j < deg; j += 128) {
        int my = s_eid[j];
        int rk = 0;
        for (int i = 0; i < deg; i++) rk += (s_eid[i] < my);
        float4 ae;
        int src;
        if (my < EE) {
            src = ei[my];
            const float* er = ea + (size_t)my*EDIM;
            float e0=0.f, e1=0.f, e2=0.f, e3=0.f;
            #pragma unroll
            for (int k = 0; k < EDIM; k++) {
                float v = er[k];
                e0 += v*s_ve[k*4+0]; e1 += v*s_ve[k*4+1];
                e2 += v*s_ve[k*4+2]; e3 += v*s_ve[k*4+3];
            }
            ae = make_float4(e0, e1, e2, e3);
        } else {
            src = my - EE;
            ae = make_float4(s_sl[0], s_sl[1], s_sl[2], s_sl[3]);
        }
        g_srcs[beg + rk] = src;
        ((float4*)g_aec)[beg + rk] = ae;
    }
}

// ---------------- per-node attention dot products ----------------
__global__ void k_nodealpha(const float* __restrict__ aS, const float* __restrict__ aD) {
    int n = blockIdx.x;
    int w = threadIdx.x >> 5, lane = threadIdx.x & 31;
    const float* hp = g_h + (size_t)n*HC + w*64;
    float v1 = hp[lane], v2 = hp[lane+32];
    float s = v1*aS[w*64+lane] + v2*aS[w*64+lane+32];
    float d = v1*aD[w*64+lane] + v2*aD[w*64+lane+32];
    #pragma unroll
    for (int o = 16; o; o >>= 1) {
        s += __shfl_xor_sync(0xffffffffu, s, o);
        d += __shfl_xor_sync(0xffffffffu, d, o);
    }
    if (lane == 0) { g_asrc[n*4+w] = s; g_adst[n*4+w] = d; }
}

// ---------------- per-dst aggregation (alpha computed inline) ----------------
__global__ void __launch_bounds__(256) k_aggregate(const int* __restrict__ ei,
                                                   const float* __restrict__ bias,
                                                   float* __restrict__ outp, int l0) {
    __shared__ int   s_src[CAP];
    __shared__ float s_a[CAP*4];
    __shared__ float s_red[8];
    __shared__ float s_amax[4];
    __shared__ float s_inv[4];

    int n = blockIdx.x;
    int t = threadIdx.x;
    int beg = g_rowptr[n];
    int deg = g_rowptr[n+1] - beg;
    if (deg > CAP) deg = CAP;

    float4 ad = ((const float4*)g_adst)[n];

    for (int j = t; j < deg; j += 256) {
        int src = g_srcs[beg + j];
        s_src[j] = src;
        float4 a = ((const float4*)g_asrc)[src];
        float al0 = a.x + ad.x, al1 = a.y + ad.y, al2 = a.z + ad.z, al3 = a.w + ad.w;
        if (l0) {
            float4 ae = ((const float4*)g_aec)[beg + j];
            al0 += ae.x; al1 += ae.y; al2 += ae.z; al3 += ae.w;
        }
        s_a[j*4+0] = (al0 >= 0.f) ? al0 : NEG*al0;
        s_a[j*4+1] = (al1 >= 0.f) ? al1 : NEG*al1;
        s_a[j*4+2] = (al2 >= 0.f) ? al2 : NEG*al2;
        s_a[j*4+3] = (al3 >= 0.f) ? al3 : NEG*al3;
    }
    __syncthreads();

    int hd = t >> 6, lane = t & 63;
    float m = -FLT_MAX;
    for (int j = lane; j < deg; j += 64) m = fmaxf(m, s_a[j*4 + hd]);
    #pragma unroll
    for (int o = 16; o; o >>= 1) m = fmaxf(m, __shfl_xor_sync(0xffffffffu, m, o));
    if ((t & 31) == 0) s_red[t >> 5] = m;
    __syncthreads();
    if (t < 4) s_amax[t] = fmaxf(s_red[2*t], s_red[2*t+1]);
    __syncthreads();
    float am = s_amax[hd];
    float sum = 0.f;
    for (int j = lane; j < deg; j += 64) {
        float ev = expf(s_a[j*4 + hd] - am);
        s_a[j*4 + hd] = ev;
        sum += ev;
    }
    #pragma unroll
    for (int o = 16; o; o >>= 1) sum += __shfl_xor_sync(0xffffffffu, sum, o);
    if ((t & 31) == 0) s_red[t >> 5] = sum;
    __syncthreads();
    if (t < 4) s_inv[t] = 1.f / ((s_red[2*t] + s_red[2*t+1]) + 1e-16f);
    __syncthreads();
    for (int j = t; j < deg; j += 256) {
        s_a[j*4+0] *= s_inv[0]; s_a[j*4+1] *= s_inv[1];
        s_a[j*4+2] *= s_inv[2]; s_a[j*4+3] *= s_inv[3];
    }
    __syncthreads();
    float acc = 0.f;
    #pragma unroll 2
    for (int j = 0; j < deg; j++) {
        float coef = s_a[j*4 + hd];
        int src = s_src[j];
        acc += coef * g_h[(size_t)src*HC + t];
    }
    outp[(size_t)n*HC + t] = acc + bias[t];
}

// ---------------- BatchNorm ----------------
__global__ void k_bnstats(const float* __restrict__ o) {
    int t = threadIdx.x, b = blockIdx.x;
    float s1 = 0.f, s2 = 0.f;
    const float* p = o + (size_t)b*250*HC + t;
    for (int rr = 0; rr < 250; rr++) {
        float v = p[(size_t)rr*HC];
        s1 += v; s2 += v*v;
    }
    g_ps1[b*HC + t] = s1;
    g_ps2[b*HC + t] = s2;
}

__global__ void k_bnfin(const float* __restrict__ gamma, const float* __restrict__ beta) {
    int t = threadIdx.x;
    float s1 = 0.f, s2 = 0.f;
    for (int b = 0; b < 200; b++) { s1 += g_ps1[b*HC + t]; s2 += g_ps2[b*HC + t]; }
    float mu  = s1 * (1.0f/NN);
    float var = s2 * (1.0f/NN) - mu*mu;
    float sc  = gamma[t] * rsqrtf(var + BNEPS);
    g_scale[t] = sc;
    g_shift[t] = beta[t] - mu*sc;
}

// BN apply + ReLU + bf16 split -> g_xs [M][512] (layers 0,1)
__global__ void k_bnapply_bf16(const float* __restrict__ o) {
    int t = threadIdx.x;
    size_t i = (size_t)blockIdx.x*HC + t;
    float v = fmaxf(o[i]*g_scale[t] + g_shift[t], 0.f);
    __nv_bfloat16 hi = __float2bfloat16_rn(v);
    g_xs[(size_t)blockIdx.x*512 + t] = hi;
    g_xs[(size_t)blockIdx.x*512 + 256 + t] = __float2bfloat16_rn(v - __bfloat162float(hi));
}

// ---------------- global mean pool fused with layer-2 BN+ReLU ----------------
__global__ void k_pool(const float* __restrict__ o, const int* __restrict__ batch,
                       float* __restrict__ out) {
    __shared__ int s_lo, s_hi;
    int g = blockIdx.x, t = threadIdx.x;
    if (t == 0) {
        int lo = 0, hi = NN;
        while (lo < hi) { int m = (lo+hi) >> 1; if (batch[m] < g) lo = m+1; else hi = m; }
        s_lo = lo;
    }
    if (t == 1) {
        int lo = 0, hi = NN;
        while (lo < hi) { int m = (lo+hi) >> 1; if (batch[m] < g+1) lo = m+1; else hi = m; }
        s_hi = lo;
    }
    __syncthreads();
    float sc = g_scale[t], sh = g_shift[t];
    float s = 0.f;
    for (int n = s_lo; n < s_hi; n++)
        s += fmaxf(o[(size_t)n*HC + t]*sc + sh, 0.f);
    int c = s_hi - s_lo;
    out[g*HC + t] = s / (float)max(c, 1);
}

// ---------------- launch ----------------
extern "C" void kernel_launch(void* const* d_in, const int* in_sizes, int n_in,
                              void* d_out, int out_size) {
    const float* x     = (const float*)d_in[0];
    const int*   ei    = (const int*)  d_in[1];
    const float* ea    = (const float*)d_in[2];
    const int*   batch = (const int*)  d_in[3];
    const float* W[3]    = {(const float*)d_in[4],  (const float*)d_in[10], (const float*)d_in[16]};
    const float* aS[3]   = {(const float*)d_in[5],  (const float*)d_in[11], (const float*)d_in[17]};
    const float* aD[3]   = {(const float*)d_in[6],  (const float*)d_in[12], (const float*)d_in[18]};
    const float* bias[3] = {(const float*)d_in[7],  (const float*)d_in[13], (const float*)d_in[19]};
    const float* gam[3]  = {(const float*)d_in[8],  (const float*)d_in[14], (const float*)d_in[20]};
    const float* bet[3]  = {(const float*)d_in[9],  (const float*)d_in[15], (const float*)d_in[21]};
    const float* We0  = (const float*)d_in[22];
    const float* atte = (const float*)d_in[23];
    float* out = (float*)d_out;

    void* p;
    float *hb, *t0;
    __nv_bfloat16 *xs, *ws;
    cudaGetSymbolAddress(&p, g_h);  hb = (float*)p;
    cudaGetSymbolAddress(&p, g_t0); t0 = (float*)p;
    cudaGetSymbolAddress(&p, g_xs); xs = (__nv_bfloat16*)p;
    cudaGetSymbolAddress(&p, g_ws); ws = (__nv_bfloat16*)p;

    int egrid = (ET + 255) / 256;
    int gtiles = (NN + 127) / 128;

    k_zero<<<NBLK_SCAN, 256>>>();
    k_edge_mean<<<256, 256>>>(ea);
    k_ve<<<1, 64>>>(We0, atte);
    k_count<<<egrid, 256>>>(ei);
    k_scan1<<<NBLK_SCAN, 256>>>();
    k_scan2<<<1, 256>>>();
    k_scan3<<<NBLK_SCAN, 256>>>();
    k_scatter<<<egrid, 256>>>(ei);
    k_sortcsr<<<NN, 128>>>(ei, ea);

    k_cvtX<<<(NN*128 + 255)/256, 256>>>(x);

    int K = 128;
    for (int l = 0; l < 3; l++) {
        k_cvtW<<<HC, K>>>(W[l], K);
        k_gemm_hmma<<<dim3(gtiles, 2), 256>>>(xs, ws, hb, NN, 2*K);
        k_nodealpha<<<NN, 128>>>(aS[l], aD[l]);
        k_aggregate<<<NN, 256>>>(ei, bias[l], t0, (l == 0) ? 1 : 0);
        k_bnstats<<<200, 256>>>(t0);
        k_bnfin<<<1, 256>>>(gam[l], bet[l]);
        if (l < 2) k_bnapply_bf16<<<NN, 256>>>(t0);
        K = HC;
    }
    k_pool<<<GG, 256>>>(t0, batch, out);
}